// round 3
// baseline (speedup 1.0000x reference)
#include <cuda_runtime.h>
#include <cstdint>

// out[i, 0:32] = weight[b[i], 0:32]  (fp32), out[0, :] = 0.
// N = 1e6 rows, Y_DIM = 32 -> 8 float4 per row, 8M float4 total.
//
// L2-resident strategy: the 128MB output ~fits in the 126MB L2; in
// graph-replay steady state dirty lines are re-dirtied in place, so we
// AVOID streaming/evict-first hints and let L2 absorb the write stream.
// Each thread handles VPT=8 float4s (stride-TPB within a 2048-vec4 block
// tile): every store is a fully-coalesced 512B warp transaction, 8
// independent load->load->store chains per thread (MLP=8).

static constexpr int Y_DIM = 32;
static constexpr int VEC_PER_ROW = Y_DIM / 4;   // 8
static constexpr int TPB = 256;
static constexpr int VPT = 8;                    // float4 per thread
static constexpr int TILE = TPB * VPT;           // 2048 vec4 per block

__global__ __launch_bounds__(TPB) void gather_rows_ilp8(
    const int* __restrict__ b,          // [N]
    const float* __restrict__ weight,   // [64, 32]
    float4* __restrict__ out,           // [N*8] float4
    int n_vec)
{
    const float4* __restrict__ w4 = reinterpret_cast<const float4*>(weight);

    int base = blockIdx.x * TILE + threadIdx.x;

    int  v[VPT];
    int  bi[VPT];
    bool ok[VPT];

    // Phase 1: indices (independent LDGs; 8 lanes share each b[row] -> L1 broadcast)
    #pragma unroll
    for (int k = 0; k < VPT; k++) {
        v[k]  = base + k * TPB;
        ok[k] = v[k] < n_vec;
        int row = v[k] >> 3;
        bi[k] = ok[k] ? __ldg(&b[row]) : 0;
    }

    // Phase 2: weight vec4s (8KB table, L1-resident)
    float4 val[VPT];
    #pragma unroll
    for (int k = 0; k < VPT; k++) {
        val[k] = __ldg(&w4[bi[k] * VEC_PER_ROW + (v[k] & 7)]);
        if ((v[k] >> 3) == 0) val[k] = make_float4(0.f, 0.f, 0.f, 0.f);
    }

    // Phase 3: plain stores -- default policy keeps dirty lines L2-resident
    #pragma unroll
    for (int k = 0; k < VPT; k++) {
        if (ok[k]) out[v[k]] = val[k];
    }
}

extern "C" void kernel_launch(void* const* d_in, const int* in_sizes, int n_in,
                              void* d_out, int out_size) {
    const int*   b      = (const int*)d_in[0];
    const float* weight = (const float*)d_in[1];
    float4*      out    = (float4*)d_out;

    int n     = in_sizes[0];          // N rows
    int n_vec = n * VEC_PER_ROW;      // 8M float4

    int blocks = (n_vec + TILE - 1) / TILE;
    gather_rows_ilp8<<<blocks, TPB>>>(b, weight, out, n_vec);
}

// round 5
// speedup vs baseline: 1.0025x; 1.0025x over previous
#include <cuda_runtime.h>
#include <cstdint>

// out[i, 0:32] = weight[b[i], 0:32] (fp32), out[0, :] = 0.
// N = 1e6 rows, 32 floats/row = 4 "octs" (8 floats, 32B) per row.
//
// LSU-issue-bound regime: minimize warp-level memory instructions per
// byte using sm_100a 256-bit vector ld/st (ld/st.global.v8.f32).
// One thread = one oct per step; 4 lanes per row; warp covers 8 rows =
// 1KB contiguous output per STG.256. VPT=4 octs/thread for MLP.

static constexpr int OCT_PER_ROW = 4;   // 32 floats / 8
static constexpr int TPB  = 256;
static constexpr int VPT  = 4;          // octs per thread
static constexpr int TILE = TPB * VPT;  // octs per block

__device__ __forceinline__ void ldg256(const float* p, float r[8]) {
    asm volatile("ld.global.nc.v8.f32 {%0,%1,%2,%3,%4,%5,%6,%7}, [%8];"
                 : "=f"(r[0]), "=f"(r[1]), "=f"(r[2]), "=f"(r[3]),
                   "=f"(r[4]), "=f"(r[5]), "=f"(r[6]), "=f"(r[7])
                 : "l"(p));
}

__device__ __forceinline__ void stg256(float* p, const float r[8]) {
    asm volatile("st.global.v8.f32 [%0], {%1,%2,%3,%4,%5,%6,%7,%8};"
                 :: "l"(p),
                    "f"(r[0]), "f"(r[1]), "f"(r[2]), "f"(r[3]),
                    "f"(r[4]), "f"(r[5]), "f"(r[6]), "f"(r[7])
                 : "memory");
}

__global__ __launch_bounds__(TPB) void gather_rows_v8(
    const int* __restrict__ b,          // [N]
    const float* __restrict__ weight,   // [64, 32]
    float* __restrict__ out,            // [N*32]
    int n_oct)                          // N * 4
{
    int base = blockIdx.x * TILE + threadIdx.x;

    int  v[VPT];
    int  bi[VPT];
    bool ok[VPT];

    // Phase 1: indices (1 warp LDG per 8 rows; 4 lanes broadcast per row)
    #pragma unroll
    for (int k = 0; k < VPT; k++) {
        v[k]  = base + k * TPB;
        ok[k] = v[k] < n_oct;
        int row = v[k] >> 2;
        bi[k] = ok[k] ? __ldg(&b[row]) : 0;
    }

    // Phase 2: weight octs (8KB table, L1-resident), 256-bit loads
    float val[VPT][8];
    #pragma unroll
    for (int k = 0; k < VPT; k++) {
        ldg256(weight + bi[k] * 32 + (v[k] & 3) * 8, val[k]);
    }

    // Row 0 forced to zero
    #pragma unroll
    for (int k = 0; k < VPT; k++) {
        if ((v[k] >> 2) == 0) {
            #pragma unroll
            for (int j = 0; j < 8; j++) val[k][j] = 0.f;
        }
    }

    // Phase 3: 256-bit stores, fully coalesced (warp = 1KB contiguous)
    #pragma unroll
    for (int k = 0; k < VPT; k++) {
        if (ok[k]) stg256(out + (size_t)v[k] * 8, val[k]);
    }
}

extern "C" void kernel_launch(void* const* d_in, const int* in_sizes, int n_in,
                              void* d_out, int out_size) {
    const int*   b      = (const int*)d_in[0];
    const float* weight = (const float*)d_in[1];
    float*       out    = (float*)d_out;

    int n     = in_sizes[0];            // N rows
    int n_oct = n * OCT_PER_ROW;        // 4M octs

    int blocks = (n_oct + TILE - 1) / TILE;
    gather_rows_v8<<<blocks, TPB>>>(b, weight, out, n_oct);
}